// round 1
// baseline (speedup 1.0000x reference)
#include <cuda_runtime.h>

// PlasticNet: T=64 steps, B=32, I=128, H=256, clip=2.0
// out = [ ys (T*B*H) | h_f (B*H) | hebb_f (B*H*H) ]  float32

static constexpr int kT = 64;
static constexpr int kB = 32;
static constexpr int kI = 128;
static constexpr int kH = 256;
static constexpr int kChunk = 64;              // presynaptic rows per CTA
static constexpr int kCtaPerSample = kH / kChunk;  // 4
static constexpr int kNCTA = kB * kCtaPerSample;   // 128
static constexpr int kThreads = 256;

// Scratch (device globals; no allocation allowed)
__device__ float g_xwi[kT * kB * kH];              // x@Wi + bi, precomputed
__device__ float g_grec[2][kB * kCtaPerSample * kH]; // per-chunk partial rec, double buffered
__device__ unsigned int g_bar;                     // grid barrier counter

// ---------------------------------------------------------------------------
// Kernel 1: xwi[t,b,k] = sum_i x[t,b,i]*Wi[i,k] + bi[k]; also resets barrier.
// ---------------------------------------------------------------------------
__global__ void xwi_kernel(const float* __restrict__ x,
                           const float* __restrict__ Wi,
                           const float* __restrict__ bi) {
    __shared__ float xs[kI];
    const int row = blockIdx.x;        // 0 .. T*B-1
    const int k = threadIdx.x;         // 0 .. 255
    if (k < kI) xs[k] = x[row * kI + k];
    if (row == 0 && k == 0) g_bar = 0u;
    __syncthreads();
    float acc = bi[k];
#pragma unroll 16
    for (int i = 0; i < kI; ++i)
        acc = fmaf(xs[i], Wi[i * kH + k], acc);
    g_xwi[row * kH + k] = acc;
}

// ---------------------------------------------------------------------------
// Kernel 2: persistent recurrence. 128 CTAs, all co-resident.
//   blockIdx = b*4 + c ; CTA owns hebb rows [c*64, c*64+64) of sample b.
//   thread t: k4 = t&63 (column group of 4), r = t>>6 (row phase 0..3)
//   owns rows i = i0 + r + 4j, j=0..15 -> 16 float4 of hebb/w/alpha in regs.
// ---------------------------------------------------------------------------
__global__ void __launch_bounds__(kThreads, 1)
plastic_kernel(const float* __restrict__ w,
               const float* __restrict__ alpha,
               const float* __restrict__ Wm,
               const float* __restrict__ bm,
               const float* __restrict__ Wf,
               const float* __restrict__ bf,
               float* __restrict__ out) {
    const int b = blockIdx.x >> 2;
    const int c = blockIdx.x & 3;
    const int t = threadIdx.x;
    const int k4 = t & 63;
    const int r = t >> 6;
    const int kcol = k4 * 4;
    const int i0 = c * kChunk;

    // Register-resident state
    float4 wr[16], ar[16], hb[16];
#pragma unroll
    for (int j = 0; j < 16; ++j) {
        const int i = i0 + r + 4 * j;
        wr[j] = *reinterpret_cast<const float4*>(&w[i * kH + kcol]);
        ar[j] = *reinterpret_cast<const float4*>(&alpha[i * kH + kcol]);
        hb[j] = make_float4(0.f, 0.f, 0.f, 0.f);
    }
    const float4 wf4 = *reinterpret_cast<const float4*>(&Wf[kcol]);
    const float4 bf4 = *reinterpret_cast<const float4*>(&bf[kcol]);
    const float bm0 = bm[0];

    __shared__ __align__(16) float hbuf[2][kH];   // h double buffer (hp / hn)
    __shared__ __align__(16) float part[4][kH];   // rec partial over row phases
    __shared__ float eta_s;

    hbuf[0][t] = 0.f;
    hbuf[1][t] = 0.f;
    __syncthreads();

    float* __restrict__ ys = out;
    float* __restrict__ hf = out + kT * kB * kH;
    float* __restrict__ hebbf = out + kT * kB * kH + kB * kH;

    for (int step = 0; step < kT; ++step) {
        const int par = step & 1;
        const float* hp = hbuf[par];
        float* hn = hbuf[par ^ 1];

        // ---- pass 1: partial rec[k] = sum_{i in chunk} hp[i]*(w+alpha*hebb) ----
        float4 pr = make_float4(0.f, 0.f, 0.f, 0.f);
#pragma unroll
        for (int j = 0; j < 16; ++j) {
            const float hpi = hp[i0 + r + 4 * j];
            float4 m;
            m.x = fmaf(ar[j].x, hb[j].x, wr[j].x);
            m.y = fmaf(ar[j].y, hb[j].y, wr[j].y);
            m.z = fmaf(ar[j].z, hb[j].z, wr[j].z);
            m.w = fmaf(ar[j].w, hb[j].w, wr[j].w);
            pr.x = fmaf(hpi, m.x, pr.x);
            pr.y = fmaf(hpi, m.y, pr.y);
            pr.z = fmaf(hpi, m.z, pr.z);
            pr.w = fmaf(hpi, m.w, pr.w);
        }
        *reinterpret_cast<float4*>(&part[r][kcol]) = pr;
        __syncthreads();
        if (r == 0) {  // t < 64: reduce 4 row phases, publish chunk partial
            const float4 p0 = *reinterpret_cast<const float4*>(&part[0][kcol]);
            const float4 p1 = *reinterpret_cast<const float4*>(&part[1][kcol]);
            const float4 p2 = *reinterpret_cast<const float4*>(&part[2][kcol]);
            const float4 p3 = *reinterpret_cast<const float4*>(&part[3][kcol]);
            float4 s;
            s.x = (p0.x + p1.x) + (p2.x + p3.x);
            s.y = (p0.y + p1.y) + (p2.y + p3.y);
            s.z = (p0.z + p1.z) + (p2.z + p3.z);
            s.w = (p0.w + p1.w) + (p2.w + p3.w);
            *reinterpret_cast<float4*>(&g_grec[par][(b * 4 + c) * kH + kcol]) = s;
        }
        __threadfence();
        __syncthreads();

        // ---- grid barrier (all 128 CTAs resident; monotonic counter) ----
        if (t == 0) {
            atomicAdd(&g_bar, 1u);
            const unsigned goal = (unsigned)kNCTA * (unsigned)(step + 1);
            while (*((volatile unsigned int*)&g_bar) < goal) { }
        }
        __syncthreads();

        // ---- compute h (each CTA redundantly; avoids a 2nd grid sync) ----
        if (t < 64) {
            const float4* gp =
                reinterpret_cast<const float4*>(&g_grec[par][b * 4 * kH]);
            const float4 s0 = __ldcg(gp + 0 * 64 + t);
            const float4 s1 = __ldcg(gp + 1 * 64 + t);
            const float4 s2 = __ldcg(gp + 2 * 64 + t);
            const float4 s3 = __ldcg(gp + 3 * 64 + t);
            const float4 xw = *reinterpret_cast<const float4*>(
                &g_xwi[(step * kB + b) * kH + t * 4]);
            float4 h4;
            h4.x = tanhf(xw.x + ((s0.x + s1.x) + (s2.x + s3.x)));
            h4.y = tanhf(xw.y + ((s0.y + s1.y) + (s2.y + s3.y)));
            h4.z = tanhf(xw.z + ((s0.z + s1.z) + (s2.z + s3.z)));
            h4.w = tanhf(xw.w + ((s0.w + s1.w) + (s2.w + s3.w)));
            *reinterpret_cast<float4*>(&hn[t * 4]) = h4;
            if (c == 0)
                *reinterpret_cast<float4*>(&ys[(step * kB + b) * kH + t * 4]) = h4;
        }
        __syncthreads();

        // ---- eta = tanh(h @ Wm + bm), one warp ----
        if (t < 32) {
            float s = 0.f;
#pragma unroll
            for (int q = 0; q < 8; ++q) {
                const int kk = q * 32 + t;
                s += hn[kk] * __ldg(&Wm[kk]);
            }
#pragma unroll
            for (int off = 16; off; off >>= 1)
                s += __shfl_xor_sync(0xffffffffu, s, off);
            if (t == 0) eta_s = tanhf(s + bm0);
        }
        __syncthreads();

        // ---- pass 2: hebb = clip(hebb + (eta*Wf+bf) * hp[i]*h[k]) ----
        const float eta = eta_s;
        const float4 h4 = *reinterpret_cast<const float4*>(&hn[kcol]);
        float4 me;
        me.x = fmaf(eta, wf4.x, bf4.x);
        me.y = fmaf(eta, wf4.y, bf4.y);
        me.z = fmaf(eta, wf4.z, bf4.z);
        me.w = fmaf(eta, wf4.w, bf4.w);
#pragma unroll
        for (int j = 0; j < 16; ++j) {
            const float hpi = hp[i0 + r + 4 * j];
            hb[j].x = fminf(fmaxf(fmaf(me.x, hpi * h4.x, hb[j].x), -2.f), 2.f);
            hb[j].y = fminf(fmaxf(fmaf(me.y, hpi * h4.y, hb[j].y), -2.f), 2.f);
            hb[j].z = fminf(fmaxf(fmaf(me.z, hpi * h4.z, hb[j].z), -2.f), 2.f);
            hb[j].w = fminf(fmaxf(fmaf(me.w, hpi * h4.w, hb[j].w), -2.f), 2.f);
        }
        // no extra sync needed: next step's first smem write (part) is followed
        // by a __syncthreads before any conflicting read; hbuf[par] is only
        // rewritten after the next grid barrier.
    }

    // ---- final outputs ----
    if (c == 0) hf[b * kH + t] = hbuf[0][t];  // T=64 even -> final h in hbuf[0]
#pragma unroll
    for (int j = 0; j < 16; ++j) {
        const int i = i0 + r + 4 * j;
        *reinterpret_cast<float4*>(
            &hebbf[(size_t)b * kH * kH + i * kH + kcol]) = hb[j];
    }
}

// ---------------------------------------------------------------------------
extern "C" void kernel_launch(void* const* d_in, const int* in_sizes, int n_in,
                              void* d_out, int out_size) {
    const float* x     = (const float*)d_in[0];
    const float* Wi    = (const float*)d_in[1];
    const float* bi    = (const float*)d_in[2];
    const float* w     = (const float*)d_in[3];
    const float* alpha = (const float*)d_in[4];
    const float* Wm    = (const float*)d_in[5];
    const float* bm    = (const float*)d_in[6];
    const float* Wf    = (const float*)d_in[7];
    const float* bf    = (const float*)d_in[8];
    float* out = (float*)d_out;

    xwi_kernel<<<kT * kB, kThreads>>>(x, Wi, bi);
    plastic_kernel<<<kNCTA, kThreads>>>(w, alpha, Wm, bm, Wf, bf, out);
}

// round 2
// speedup vs baseline: 1.5793x; 1.5793x over previous
#include <cuda_runtime.h>

// PlasticNet: T=64 steps, B=32, I=128, H=256, clip=2.0
// out = [ ys (T*B*H) | h_f (B*H) | hebb_f (B*H*H) ]  float32

static constexpr int kT = 64;
static constexpr int kB = 32;
static constexpr int kI = 128;
static constexpr int kH = 256;
static constexpr int kChunk = 64;                  // presynaptic rows per CTA
static constexpr int kCtaPerSample = kH / kChunk;  // 4 = cluster size
static constexpr int kNCTA = kB * kCtaPerSample;   // 128
static constexpr int kThreads = 256;

// Scratch (device globals; no allocation allowed)
__device__ float g_xwi[kT * kB * kH];              // x@Wi + bi, precomputed

// ---------------------------------------------------------------------------
// Kernel 1: xwi[t,b,k] = sum_i x[t,b,i]*Wi[i,k] + bi[k]
// ---------------------------------------------------------------------------
__global__ void xwi_kernel(const float* __restrict__ x,
                           const float* __restrict__ Wi,
                           const float* __restrict__ bi) {
    __shared__ float xs[kI];
    const int row = blockIdx.x;        // 0 .. T*B-1
    const int k = threadIdx.x;         // 0 .. 255
    if (k < kI) xs[k] = x[row * kI + k];
    __syncthreads();
    float acc = bi[k];
#pragma unroll 16
    for (int i = 0; i < kI; ++i)
        acc = fmaf(xs[i], Wi[i * kH + k], acc);
    g_xwi[row * kH + k] = acc;
}

// ---------------------------------------------------------------------------
// DSMEM helpers
// ---------------------------------------------------------------------------
__device__ __forceinline__ unsigned smem_u32(const void* p) {
    return (unsigned)__cvta_generic_to_shared(p);
}
__device__ __forceinline__ void dsmem_st4(unsigned local_addr, unsigned rank,
                                          float4 v) {
    unsigned remote;
    asm volatile("mapa.shared::cluster.u32 %0, %1, %2;"
                 : "=r"(remote) : "r"(local_addr), "r"(rank));
    asm volatile("st.shared::cluster.v4.f32 [%0], {%1,%2,%3,%4};"
                 :: "r"(remote), "f"(v.x), "f"(v.y), "f"(v.z), "f"(v.w)
                 : "memory");
}
__device__ __forceinline__ void cluster_sync_all() {
    asm volatile("barrier.cluster.arrive.aligned;" ::: "memory");
    asm volatile("barrier.cluster.wait.aligned;" ::: "memory");
}

// ---------------------------------------------------------------------------
// Kernel 2: persistent recurrence. 128 CTAs = 32 clusters of 4 (one / sample).
//   blockIdx = b*4 + c ; CTA owns hebb rows [c*64, c*64+64) of sample b.
//   thread t: k4 = t&63 (column group of 4), r = t>>6 (row phase 0..3)
//   owns rows i = i0 + r + 4j, j=0..15 -> 16 float4 of hebb/w/alpha in regs.
// Per step the 4 CTAs exchange their 256-wide rec partials via DSMEM, then
// every CTA redundantly computes h / eta from local SMEM.
// ---------------------------------------------------------------------------
__global__ void __launch_bounds__(kThreads, 1) __cluster_dims__(kCtaPerSample, 1, 1)
plastic_kernel(const float* __restrict__ w,
               const float* __restrict__ alpha,
               const float* __restrict__ Wm,
               const float* __restrict__ bm,
               const float* __restrict__ Wf,
               const float* __restrict__ bf,
               float* __restrict__ out) {
    const int b = blockIdx.x >> 2;
    const int c = blockIdx.x & 3;      // == cluster ctarank (contiguous x split)
    const int t = threadIdx.x;
    const int k4 = t & 63;
    const int r = t >> 6;
    const int kcol = k4 * 4;
    const int i0 = c * kChunk;
    const int lane = t & 31;

    // Register-resident state
    float4 wr[16], ar[16], hb[16];
#pragma unroll
    for (int j = 0; j < 16; ++j) {
        const int i = i0 + r + 4 * j;
        wr[j] = *reinterpret_cast<const float4*>(&w[i * kH + kcol]);
        ar[j] = *reinterpret_cast<const float4*>(&alpha[i * kH + kcol]);
        hb[j] = make_float4(0.f, 0.f, 0.f, 0.f);
    }
    const float4 wf4 = *reinterpret_cast<const float4*>(&Wf[kcol]);
    const float4 bf4 = *reinterpret_cast<const float4*>(&bf[kcol]);
    const float bm0 = bm[0];

    __shared__ __align__(16) float hbuf[2][kH];        // h double buffer
    __shared__ __align__(16) float part[4][kH];        // intra-CTA row phases
    __shared__ __align__(16) float recv[2][4][kH];     // cluster partials (dbl buf)

    hbuf[0][t] = 0.f;
    hbuf[1][t] = 0.f;
    __syncthreads();
    cluster_sync_all();   // recv buffers exist in all peers before any push

    float* __restrict__ ys = out;
    float* __restrict__ hf = out + kT * kB * kH;
    float* __restrict__ hebbf = out + kT * kB * kH + kB * kH;

    const float* xwp = g_xwi + b * kH + t;             // stride kB*kH per step
    float* ysp = ys + b * kH + t;

    for (int step = 0; step < kT; ++step) {
        const int par = step & 1;
        const float* hp = hbuf[par];
        float* hn = hbuf[par ^ 1];

        // ---- pass 1: partial rec[k] over this CTA's 64 presynaptic rows ----
        float4 pr = make_float4(0.f, 0.f, 0.f, 0.f);
#pragma unroll
        for (int j = 0; j < 16; ++j) {
            const float hpi = hp[i0 + r + 4 * j];      // warp-uniform broadcast
            float4 m;
            m.x = fmaf(ar[j].x, hb[j].x, wr[j].x);
            m.y = fmaf(ar[j].y, hb[j].y, wr[j].y);
            m.z = fmaf(ar[j].z, hb[j].z, wr[j].z);
            m.w = fmaf(ar[j].w, hb[j].w, wr[j].w);
            pr.x = fmaf(hpi, m.x, pr.x);
            pr.y = fmaf(hpi, m.y, pr.y);
            pr.z = fmaf(hpi, m.z, pr.z);
            pr.w = fmaf(hpi, m.w, pr.w);
        }
        *reinterpret_cast<float4*>(&part[r][kcol]) = pr;
        __syncthreads();

        // ---- reduce 4 row phases; push chunk partial to all 4 cluster CTAs ----
        if (t < 64) {
            const float4 p0 = *reinterpret_cast<const float4*>(&part[0][kcol]);
            const float4 p1 = *reinterpret_cast<const float4*>(&part[1][kcol]);
            const float4 p2 = *reinterpret_cast<const float4*>(&part[2][kcol]);
            const float4 p3 = *reinterpret_cast<const float4*>(&part[3][kcol]);
            float4 s;
            s.x = (p0.x + p1.x) + (p2.x + p3.x);
            s.y = (p0.y + p1.y) + (p2.y + p3.y);
            s.z = (p0.z + p1.z) + (p2.z + p3.z);
            s.w = (p0.w + p1.w) + (p2.w + p3.w);
            // local copy
            *reinterpret_cast<float4*>(&recv[par][c][kcol]) = s;
            // remote copies (3 peers)
            const unsigned laddr = smem_u32(&recv[par][c][kcol]);
#pragma unroll
            for (int d = 1; d < 4; ++d)
                dsmem_st4(laddr, (unsigned)((c + d) & 3), s);
        }

        // prefetch xwi under the barrier latency
        const float xw = __ldg(xwp + step * (kB * kH));

        // ---- cluster barrier: all partials delivered (release/acquire) ----
        cluster_sync_all();

        // ---- h: all 256 threads, one element each, from local SMEM ----
        const float hsum = (recv[par][0][t] + recv[par][1][t]) +
                           (recv[par][2][t] + recv[par][3][t]);
        const float h = tanhf(xw + hsum);
        hn[t] = h;
        if (c == 0) ysp[step * (kB * kH)] = h;
        __syncthreads();

        // ---- eta = tanh(h @ Wm + bm): redundant per warp, no broadcast ----
        float s = 0.f;
#pragma unroll
        for (int q = 0; q < 8; ++q) {
            const int kk = q * 32 + lane;
            s = fmaf(hn[kk], __ldg(&Wm[kk]), s);
        }
#pragma unroll
        for (int off = 16; off; off >>= 1)
            s += __shfl_xor_sync(0xffffffffu, s, off);
        const float eta = tanhf(s + bm0);

        // ---- pass 2: hebb = clip(hebb + (eta*Wf+bf) * hp[i]*h[k]) ----
        const float4 h4 = *reinterpret_cast<const float4*>(&hn[kcol]);
        float4 me;
        me.x = fmaf(eta, wf4.x, bf4.x);
        me.y = fmaf(eta, wf4.y, bf4.y);
        me.z = fmaf(eta, wf4.z, bf4.z);
        me.w = fmaf(eta, wf4.w, bf4.w);
#pragma unroll
        for (int j = 0; j < 16; ++j) {
            const float hpi = hp[i0 + r + 4 * j];
            hb[j].x = fminf(fmaxf(fmaf(me.x, hpi * h4.x, hb[j].x), -2.f), 2.f);
            hb[j].y = fminf(fmaxf(fmaf(me.y, hpi * h4.y, hb[j].y), -2.f), 2.f);
            hb[j].z = fminf(fmaxf(fmaf(me.z, hpi * h4.z, hb[j].z), -2.f), 2.f);
            hb[j].w = fminf(fmaxf(fmaf(me.w, hpi * h4.w, hb[j].w), -2.f), 2.f);
        }
        // next iteration's part[] write is fenced by the __syncthreads after it;
        // hbuf[par] is only overwritten after the next cluster sync.
    }

    // ---- final outputs ----
    if (c == 0) hf[b * kH + t] = hbuf[0][t];  // T=64 even -> final h in hbuf[0]
#pragma unroll
    for (int j = 0; j < 16; ++j) {
        const int i = i0 + r + 4 * j;
        *reinterpret_cast<float4*>(
            &hebbf[(size_t)b * kH * kH + i * kH + kcol]) = hb[j];
    }
}

// ---------------------------------------------------------------------------
extern "C" void kernel_launch(void* const* d_in, const int* in_sizes, int n_in,
                              void* d_out, int out_size) {
    const float* x     = (const float*)d_in[0];
    const float* Wi    = (const float*)d_in[1];
    const float* bi    = (const float*)d_in[2];
    const float* w     = (const float*)d_in[3];
    const float* alpha = (const float*)d_in[4];
    const float* Wm    = (const float*)d_in[5];
    const float* bm    = (const float*)d_in[6];
    const float* Wf    = (const float*)d_in[7];
    const float* bf    = (const float*)d_in[8];
    float* out = (float*)d_out;

    xwi_kernel<<<kT * kB, kThreads>>>(x, Wi, bi);
    plastic_kernel<<<kNCTA, kThreads>>>(w, alpha, Wm, bm, Wf, bf, out);
}